// round 4
// baseline (speedup 1.0000x reference)
#include <cuda_runtime.h>
#include <math_constants.h>

// GATv2 additive attention + masked softmax, mask-compacted.
// score(b,h,i,j) = sum_d a[h,d] * silu(q[b,h,i,d] + k[b,h,j,d])
// silu(s) = u*(1+tanh(u)), u=s/2; q,k pre-scaled by 0.5 at staging.
// Only unmasked j (~50%) get scores computed: per-warp index compaction
// via ballot + __fns, scores scattered back to dense via reused smem.

#define B_   2
#define H_   8
#define LQ_  384
#define LK_  384
#define D_   64
#define ROWS 8          // q rows per block, 1 warp per row
#define PAD  68         // K smem row stride (words)
#define NC   12         // LK/32 chunks

__device__ __forceinline__ float tanh_approx(float x) {
    float r;
    asm("tanh.approx.f32 %0, %1;" : "=f"(r) : "f"(x));
    return r;
}

__global__ __launch_bounds__(256, 2)
void gatv2_kernel(const float* __restrict__ q, const float* __restrict__ k,
                  const float* __restrict__ att, const int* __restrict__ mask,
                  float* __restrict__ out)
{
    extern __shared__ float smem[];
    float* ks = smem;                    // [LK][PAD] (0.5*k); reused as scatter buf after barrier
    float* qs = ks + LK_ * PAD;          // [ROWS][PAD] (0.5*q)
    float* as = qs + ROWS * PAD;         // [D]

    const int ntiles = LQ_ / ROWS;       // 48
    int blk   = blockIdx.x;
    int bh    = blk / ntiles;
    int itile = blk - bh * ntiles;
    int h     = bh & (H_ - 1);
    int tid   = threadIdx.x;

    // ---- stage 0.5*K tile ----
    const float4* kg = (const float4*)(k + (size_t)bh * LK_ * D_);
    for (int idxr = tid; idxr < LK_ * D_ / 4; idxr += 256) {
        int j = idxr >> 4, d4 = idxr & 15;
        float4 v = kg[idxr];
        v.x *= 0.5f; v.y *= 0.5f; v.z *= 0.5f; v.w *= 0.5f;
        *(float4*)(ks + j * PAD + d4 * 4) = v;
    }
    // ---- stage 0.5*q rows ----
    const float4* qg = (const float4*)(q + ((size_t)bh * LQ_ + itile * ROWS) * D_);
    for (int idxr = tid; idxr < ROWS * D_ / 4; idxr += 256) {
        int i = idxr >> 4, d4 = idxr & 15;
        float4 v = qg[idxr];
        v.x *= 0.5f; v.y *= 0.5f; v.z *= 0.5f; v.w *= 0.5f;
        *(float4*)(qs + i * PAD + d4 * 4) = v;
    }
    if (tid < D_) as[tid] = att[h * D_ + tid];
    __syncthreads();

    int warp = tid >> 5, lane = tid & 31;
    int i = itile * ROWS + warp;
    const float* qrow = qs + warp * PAD;

    // ---- mask ballots + compaction (registers only) ----
    const int* mrow = mask + ((size_t)bh * LQ_ + i) * LK_;
    unsigned bal[NC];
    int nkeep = 0;
#pragma unroll
    for (int c = 0; c < NC; c++) {
        int keep = (mrow[c * 32 + lane] == 0);
        bal[c] = __ballot_sync(0xffffffffu, keep);
        nkeep += __popc(bal[c]);
    }
    int nchunk = (nkeep + 31) >> 5;

    // idx[cc] = dense j of the (cc*32+lane)-th unmasked column
    int idx[NC];
#pragma unroll
    for (int cc = 0; cc < NC; cc++) {
        int r = cc * 32 + lane;
        int id = 0;
        if (r < nkeep) {
#pragma unroll
            for (int w = 0; w < NC; w++) {
                int cnt = __popc(bal[w]);
                if (r >= 0 && r < cnt) id = w * 32 + __fns(bal[w], 0, r + 1);
                r -= cnt;
            }
        }
        idx[cc] = id;
    }

    // ---- compacted score computation ----
    float acc[NC];
#pragma unroll
    for (int cc = 0; cc < NC; cc++) acc[cc] = -CUDART_INF_F;

#pragma unroll
    for (int cc = 0; cc < NC; cc++) {
        if (cc < nchunk) {                      // uniform branch per warp
            const float* krow = ks + idx[cc] * PAD;
            float ax = 0.f, ay = 0.f, az = 0.f, aw = 0.f;
#pragma unroll
            for (int d4 = 0; d4 < D_ / 4; d4++) {
                float4 q4 = *(const float4*)(qrow + d4 * 4);
                float4 a4 = *(const float4*)(as + d4 * 4);
                float4 k4 = *(const float4*)(krow + d4 * 4);
                float u, t;
                u = q4.x + k4.x; t = tanh_approx(u); ax = fmaf(a4.x, fmaf(u, t, u), ax);
                u = q4.y + k4.y; t = tanh_approx(u); ay = fmaf(a4.y, fmaf(u, t, u), ay);
                u = q4.z + k4.z; t = tanh_approx(u); az = fmaf(a4.z, fmaf(u, t, u), az);
                u = q4.w + k4.w; t = tanh_approx(u); aw = fmaf(a4.w, fmaf(u, t, u), aw);
            }
            acc[cc] = (cc * 32 + lane < nkeep) ? ((ax + ay) + (az + aw)) : -CUDART_INF_F;
        }
    }

    // ---- softmax over compacted values ----
    float mx = -CUDART_INF_F;
#pragma unroll
    for (int cc = 0; cc < NC; cc++) mx = fmaxf(mx, acc[cc]);
#pragma unroll
    for (int o = 16; o; o >>= 1) mx = fmaxf(mx, __shfl_xor_sync(0xffffffffu, mx, o));

    float sum = 0.f;
#pragma unroll
    for (int cc = 0; cc < NC; cc++) {
        float e = __expf(acc[cc] - mx);   // -inf slots -> 0 (nkeep>0); nkeep==0 -> NaN, never written
        acc[cc] = e;
        sum += e;
    }
#pragma unroll
    for (int o = 16; o; o >>= 1) sum += __shfl_xor_sync(0xffffffffu, sum, o);
    float inv = (sum > 0.f) ? __fdividef(1.f, sum) : 0.f;

    // ---- scatter to dense via reused K smem, then dense store ----
    __syncthreads();                      // everyone done reading ks
    float* ws = ks + warp * LK_;          // 384 floats per warp inside old K region
#pragma unroll
    for (int cc = 0; cc < NC; cc++) {
        if (cc * 32 + lane < nkeep) ws[idx[cc]] = acc[cc] * inv;
    }
    __syncwarp();

    float* orow = out + ((size_t)bh * LQ_ + i) * LK_;
#pragma unroll
    for (int c = 0; c < NC; c++) {
        int keep = (bal[c] >> lane) & 1;
        orow[c * 32 + lane] = keep ? ws[c * 32 + lane] : 0.f;
    }
}

extern "C" void kernel_launch(void* const* d_in, const int* in_sizes, int n_in,
                              void* d_out, int out_size)
{
    const float* q   = (const float*)d_in[0];
    const float* k   = (const float*)d_in[1];
    const float* att = (const float*)d_in[2];
    const int*   m   = (const int*)d_in[3];
    float* out       = (float*)d_out;

    const int smem_bytes = (LK_ * PAD + ROWS * PAD + D_) * (int)sizeof(float); // 106880
    cudaFuncSetAttribute(gatv2_kernel, cudaFuncAttributeMaxDynamicSharedMemorySize, smem_bytes);

    dim3 grid(B_ * H_ * (LQ_ / ROWS));   // 768
    gatv2_kernel<<<grid, 256, smem_bytes>>>(q, k, att, m, out);
}

// round 5
// speedup vs baseline: 1.3122x; 1.3122x over previous
#include <cuda_runtime.h>
#include <math_constants.h>

// GATv2 additive attention + masked softmax, mask-compacted v2.
// score(b,h,i,j) = sum_d a[h,d] * silu(q[b,h,i,d] + k[b,h,j,d])
// silu(s) = u*(1+tanh(u)), u=s/2; q,k pre-scaled by 0.5 at staging.
// ~50% of j are masked -> per-warp compaction via ballot+popc scatter into a
// per-warp uint16 smem stripe (O(12) instrs), then chunk-pair score loop.

#define B_   2
#define H_   8
#define LQ_  384
#define LK_  384
#define D_   64
#define ROWS 8          // q rows per block, 1 warp per row
#define PAD  68         // K smem row stride in words (16B-aligned rows, 8 bank blocks)
#define NC   12         // LK/32 chunks

__device__ __forceinline__ float tanh_approx(float x) {
    float r;
    asm("tanh.approx.f32 %0, %1;" : "=f"(r) : "f"(x));
    return r;
}

__global__ __launch_bounds__(256, 2)
void gatv2_kernel(const float* __restrict__ q, const float* __restrict__ k,
                  const float* __restrict__ att, const int* __restrict__ mask,
                  float* __restrict__ out)
{
    extern __shared__ float smem[];
    float* ks = smem;                    // [LK][PAD] (0.5*k); reused as scatter buf after barrier2
    float* qs = ks + LK_ * PAD;          // [ROWS][PAD] (0.5*q)
    float* as = qs + ROWS * PAD;         // [D]
    unsigned short* idxb = (unsigned short*)(as + D_);   // [ROWS][LK] compacted j indices

    const int ntiles = LQ_ / ROWS;       // 48
    int blk   = blockIdx.x;
    int bh    = blk / ntiles;
    int itile = blk - bh * ntiles;
    int h     = bh & (H_ - 1);
    int tid   = threadIdx.x;
    int warp  = tid >> 5, lane = tid & 31;
    int i     = itile * ROWS + warp;     // global q row owned by this warp

    // ---- 1. mask ballot + compaction scatter (cheap: ~7 instrs/chunk) ----
    const int* mrow = mask + ((size_t)bh * LQ_ + i) * LK_;
    unsigned short* stripe = idxb + warp * LK_;
    int base = 0;
#pragma unroll
    for (int c = 0; c < NC; c++) {
        int j = c * 32 + lane;
        int keep = (mrow[j] == 0);
        unsigned b = __ballot_sync(0xffffffffu, keep);
        if (keep) stripe[base + __popc(b & ((1u << lane) - 1u))] = (unsigned short)j;
        base += __popc(b);
    }
    int nkeep  = base;                   // uniform per warp
    int nchunk = (nkeep + 31) >> 5;

    // ---- 2. stage 0.5*K tile, 0.5*q rows, a ----
    const float4* kg = (const float4*)(k + (size_t)bh * LK_ * D_);
    for (int idxr = tid; idxr < LK_ * D_ / 4; idxr += 256) {
        int j = idxr >> 4, d4 = idxr & 15;
        float4 v = kg[idxr];
        v.x *= 0.5f; v.y *= 0.5f; v.z *= 0.5f; v.w *= 0.5f;
        *(float4*)(ks + j * PAD + d4 * 4) = v;
    }
    const float4* qg = (const float4*)(q + ((size_t)bh * LQ_ + itile * ROWS) * D_);
    for (int idxr = tid; idxr < ROWS * D_ / 4; idxr += 256) {
        int r = idxr >> 4, d4 = idxr & 15;
        float4 v = qg[idxr];
        v.x *= 0.5f; v.y *= 0.5f; v.z *= 0.5f; v.w *= 0.5f;
        *(float4*)(qs + r * PAD + d4 * 4) = v;
    }
    if (tid < D_) as[tid] = att[h * D_ + tid];
    __syncthreads();

    // ---- 3. load compacted indices into registers (clamp garbage slots) ----
    int jdx[NC];
#pragma unroll
    for (int cc = 0; cc < NC; cc++) {
        int slot = cc * 32 + lane;
        int v = (int)stripe[slot];
        jdx[cc] = (slot < nkeep) ? v : 0;   // clamped -> row 0 broadcast, result discarded
    }

    const float* qrow = qs + warp * PAD;
    float acc[NC];
#pragma unroll
    for (int cc = 0; cc < NC; cc++) acc[cc] = -CUDART_INF_F;

    // ---- 4. chunk-pair score loop: 8 independent chains, d4 inner unrolled ----
#pragma unroll
    for (int p = 0; p < NC / 2; p++) {
        if (2 * p < nchunk) {               // uniform per warp
            const float* kr0 = ks + jdx[2 * p]     * PAD;
            const float* kr1 = ks + jdx[2 * p + 1] * PAD;
            float s0 = 0.f, s1 = 0.f, s2 = 0.f, s3 = 0.f;
            float s4 = 0.f, s5 = 0.f, s6 = 0.f, s7 = 0.f;
#pragma unroll
            for (int d4 = 0; d4 < D_ / 4; d4++) {
                float4 q4 = *(const float4*)(qrow + 4 * d4);
                float4 a4 = *(const float4*)(as   + 4 * d4);
                float4 ka = *(const float4*)(kr0  + 4 * d4);
                float4 kb = *(const float4*)(kr1  + 4 * d4);
                float u, t;
                u = q4.x + ka.x; t = tanh_approx(u); s0 = fmaf(a4.x, fmaf(u, t, u), s0);
                u = q4.y + ka.y; t = tanh_approx(u); s1 = fmaf(a4.y, fmaf(u, t, u), s1);
                u = q4.z + ka.z; t = tanh_approx(u); s2 = fmaf(a4.z, fmaf(u, t, u), s2);
                u = q4.w + ka.w; t = tanh_approx(u); s3 = fmaf(a4.w, fmaf(u, t, u), s3);
                u = q4.x + kb.x; t = tanh_approx(u); s4 = fmaf(a4.x, fmaf(u, t, u), s4);
                u = q4.y + kb.y; t = tanh_approx(u); s5 = fmaf(a4.y, fmaf(u, t, u), s5);
                u = q4.z + kb.z; t = tanh_approx(u); s6 = fmaf(a4.z, fmaf(u, t, u), s6);
                u = q4.w + kb.w; t = tanh_approx(u); s7 = fmaf(a4.w, fmaf(u, t, u), s7);
            }
            acc[2 * p]     = ((2 * p)     * 32 + lane < nkeep) ? ((s0 + s1) + (s2 + s3)) : -CUDART_INF_F;
            acc[2 * p + 1] = ((2 * p + 1) * 32 + lane < nkeep) ? ((s4 + s5) + (s6 + s7)) : -CUDART_INF_F;
        }
    }

    // ---- 5. softmax over compacted values (registers + shfl only) ----
    float mx = -CUDART_INF_F;
#pragma unroll
    for (int cc = 0; cc < NC; cc++) mx = fmaxf(mx, acc[cc]);
#pragma unroll
    for (int o = 16; o; o >>= 1) mx = fmaxf(mx, __shfl_xor_sync(0xffffffffu, mx, o));

    float sum = 0.f;
#pragma unroll
    for (int cc = 0; cc < NC; cc++) {
        float e = __expf(acc[cc] - mx);   // -inf slots -> 0 (nkeep>0); nkeep==0 never stored
        acc[cc] = e;
        sum += e;
    }
#pragma unroll
    for (int o = 16; o; o >>= 1) sum += __shfl_xor_sync(0xffffffffu, sum, o);
    float inv = (sum > 0.f) ? __fdividef(1.f, sum) : 0.f;

    // ---- 6. scatter to dense via reused K smem, then dense store ----
    __syncthreads();                      // all warps done reading ks
    float* ws = ks + warp * LK_;          // private 384-float stripe
#pragma unroll
    for (int c = 0; c < NC; c++) ws[c * 32 + lane] = 0.f;
    __syncwarp();
#pragma unroll
    for (int cc = 0; cc < NC; cc++) {
        if (cc * 32 + lane < nkeep) ws[jdx[cc]] = acc[cc] * inv;
    }
    __syncwarp();

    float* orow = out + ((size_t)bh * LQ_ + i) * LK_;
#pragma unroll
    for (int c = 0; c < NC; c++) orow[c * 32 + lane] = ws[c * 32 + lane];
}

extern "C" void kernel_launch(void* const* d_in, const int* in_sizes, int n_in,
                              void* d_out, int out_size)
{
    const float* q   = (const float*)d_in[0];
    const float* k   = (const float*)d_in[1];
    const float* att = (const float*)d_in[2];
    const int*   m   = (const int*)d_in[3];
    float* out       = (float*)d_out;

    // floats: K 384*68 + q 8*68 + a 64 = 26720 -> 106880 B; + idx16 8*384*2 = 6144 B
    const int smem_bytes = (LK_ * PAD + ROWS * PAD + D_) * (int)sizeof(float)
                         + ROWS * LK_ * (int)sizeof(unsigned short);   // 113024
    cudaFuncSetAttribute(gatv2_kernel, cudaFuncAttributeMaxDynamicSharedMemorySize, smem_bytes);

    dim3 grid(B_ * H_ * (LQ_ / ROWS));   // 768
    gatv2_kernel<<<grid, 256, smem_bytes>>>(q, k, att, m, out);
}